// round 13
// baseline (speedup 1.0000x reference)
#include <cuda_runtime.h>

constexpr int HH = 512;
constexpr int WW = 512;
constexpr int NB = 9;
constexpr int OH = 32;
constexpr int OW = 32;
constexpr int BMAX = 8;

#define PIF 3.14159265358979323846f

// ---------------- scratch ----------------
__device__ float2 g_vab[BMAX * HH * WW];           // (wa*I, wb*I) per pixel
__device__ unsigned char g_k0[BMAX * HH * WW];     // base bin in [0,7]
__device__ float g_hog [BMAX * NB * OH * OW];
__device__ float g_maxn[BMAX];                     // atomicMax accumulator (>=0)
__device__ float g_tmp [BMAX * 2 * OH * WW];       // horizontally-resized rows
__device__ float g_wt  [WW * 6];
__device__ int   g_ws  [WW];

// ---------------- fused grayscale + gradient + bin decomposition (+ lanczos wt fold) ----------------
__global__ void grad_kernel(const float* __restrict__ x) {
    __shared__ float sg[10][34];
    int b = blockIdx.z;
    int x0 = blockIdx.x * 32, y0 = blockIdx.y * 8;
    const float* xb = x + (size_t)b * 3 * HH * WW;
    int tid = threadIdx.y * 32 + threadIdx.x;

    if (tid == 0) g_maxn[b] = 0.0f;   // reset for hog's atomicMax

    // fold: lanczos3 weight table, computed once by the first row of blocks of batch 0
    if (blockIdx.z == 0 && blockIdx.y == 0) {
        int o = blockIdx.x * 256 + tid;
        if (o < WW) {
            float sf = (o + 0.5f) * 0.0625f - 0.5f;
            int i0 = (int)floorf(sf) - 2;
            float w[6];
            float tot = 0.0f;
#pragma unroll
            for (int j = 0; j < 6; j++) {
                int ii = i0 + j;
                float val = 0.0f;
                if (ii >= 0 && ii < OW) {
                    float xx = fabsf(sf - (float)ii);
                    float px1 = PIF * xx;
                    float s1 = (xx == 0.0f) ? 1.0f : (sinf(px1) / px1);
                    float x3 = xx / 3.0f;
                    float px3 = PIF * x3;
                    float s3 = (x3 == 0.0f) ? 1.0f : (sinf(px3) / px3);
                    val = 3.0f * s1 * s3;
                }
                w[j] = val;
                tot += val;
            }
#pragma unroll
            for (int j = 0; j < 6; j++) g_wt[o * 6 + j] = w[j] / tot;
            g_ws[o] = i0;
        }
    }

    for (int i = tid; i < 10 * 34; i += 256) {
        int ly = i / 34, lx = i - ly * 34;
        int gy = y0 + ly - 1, gx = x0 + lx - 1;
        float v = 0.0f;
        if (gy >= 0 && gy < HH && gx >= 0 && gx < WW) {
            int p = gy * WW + gx;
            v = 0.299f * xb[p] + 0.587f * xb[p + HH * WW] + 0.114f * xb[p + 2 * HH * WW];
        }
        sg[ly][lx] = v;
    }
    __syncthreads();

    int lx = threadIdx.x, ly = threadIdx.y;
    float gx = sg[ly + 1][lx + 2] - sg[ly + 1][lx];
    float gy = sg[ly + 2][lx + 1] - sg[ly][lx + 1];
    float inten = sqrtf(gx * gx + gy * gy);
    float a = atan2f(gy, gx) + PIF;      // >= 0
    float r = fmodf(a, PIF);             // jnp.mod (positive arg) == fmod
    float o = r / PIF * 180.0f;          // [0,180)

    int k0 = (int)floorf((o - 10.0f) * 0.05f);   // [-1,8]
    float c0 = 10.0f + 20.0f * (float)k0;
    float wa = fminf(fmaxf(1.0f - (fabsf(o - c0) * 9.0f) / 180.0f, 0.0f), 1.0f);
    float wb = fminf(fmaxf(1.0f - (fabsf(o - (c0 + 20.0f)) * 9.0f) / 180.0f, 0.0f), 1.0f);
    float va = wa * inten, vb = wb * inten;
    if (k0 < 0)      { k0 = 0; va = vb; vb = 0.0f; }
    else if (k0 > 7) { k0 = 7; vb = va; va = 0.0f; }

    int p = b * HH * WW + (y0 + ly) * WW + (x0 + lx);
    g_vab[p] = make_float2(va, vb);
    g_k0[p] = (unsigned char)k0;
}

__device__ __forceinline__ int refl(int m) {
    m = (m < 0) ? -m : m;
    m = (m > HH - 1) ? (2 * (HH - 1) - m) : m;
    return m;
}

// ---------------- HOG aggregation + fused per-cell norm -> atomicMax ----------------
__global__ void hog_kernel() {
    __shared__ float sacc[NB][256];     // bank(tid) independent of bin -> conflict-free
    __shared__ int srow[33], scol[33];
    __shared__ float sbin[NB];
    int b = blockIdx.y;
    int cell = blockIdx.x;
    int oy = cell >> 5, ox = cell & 31;
    int tid = threadIdx.x;

    if (tid < 33) {
        srow[tid] = refl(oy * 16 - 16 + tid) * WW;
        scol[tid] = refl(ox * 16 - 16 + tid);
    }
#pragma unroll
    for (int k = 0; k < NB; k++) sacc[k][tid] = 0.0f;
    __syncthreads();

    const float2* __restrict__ V = g_vab + b * HH * WW;
    const unsigned char* __restrict__ K = g_k0 + b * HH * WW;

    // 1089 taps: 4 per thread + tail of 65
    float2 v[4]; float f[4]; int kk[4];
#pragma unroll
    for (int j = 0; j < 4; j++) {
        int t = tid + j * 256;
        int dy = t / 33;
        int dx = t - dy * 33;
        int gi = srow[dy] + scol[dx];
        v[j] = __ldg(&V[gi]);
        kk[j] = (int)K[gi];
        float fy = (float)(dy - 16), fx = (float)(dx - 16);
        f[j] = 1.0f - sqrtf(fy * fy + fx * fx) / 22.627417f;
    }
#pragma unroll
    for (int j = 0; j < 4; j++) {
        sacc[kk[j]][tid]     += f[j] * v[j].x;
        sacc[kk[j] + 1][tid] += f[j] * v[j].y;
    }
    if (tid < 65) {
        int t = 1024 + tid;
        int dy = t / 33;
        int dx = t - dy * 33;
        int gi = srow[dy] + scol[dx];
        float2 vt = __ldg(&V[gi]);
        int kt = (int)K[gi];
        float fy = (float)(dy - 16), fx = (float)(dx - 16);
        float ft = 1.0f - sqrtf(fy * fy + fx * fx) / 22.627417f;
        sacc[kt][tid]     += ft * vt.x;
        sacc[kt + 1][tid] += ft * vt.y;
    }
    __syncthreads();

    // warp w reduces bins k = w, w+8 (strided LDS + shuffle tree)
    int w = tid >> 5, l = tid & 31;
    for (int k = w; k < NB; k += 8) {
        float s = 0.0f;
#pragma unroll
        for (int i = 0; i < 8; i++) s += sacc[k][l + 32 * i];
#pragma unroll
        for (int off = 16; off > 0; off >>= 1)
            s += __shfl_down_sync(0xffffffffu, s, off);
        if (l == 0) {
            g_hog[(b * NB + k) * (OH * OW) + cell] = s;
            sbin[k] = s;
        }
    }
    __syncthreads();

    // cell L2 norm over bins -> per-batch max (atomic on int view; all values >= 0)
    if (tid == 0) {
        float s2 = 0.0f;
#pragma unroll
        for (int k = 0; k < NB; k++) s2 += sbin[k] * sbin[k];
        atomicMax((int*)&g_maxn[b], __float_as_int(sqrtf(s2)));
    }
}

// ---------------- fused dominant-direction + quantize + horizontal lanczos pass ----------------
// block = (row, b): dom for 32 cells of this row (threads 0-31), then hpass 2ch x 512.
__global__ void domh_kernel() {
    __shared__ float qs[2][OW];
    int b = blockIdx.y;
    int row = blockIdx.x;              // 0..31
    int tid = threadIdx.x;             // 256

    if (tid < OW) {
        int p = row * OW + tid;
        float maxn = g_maxn[b];
        float A = 0.0f, Cc = 0.0f, Bs = 0.0f;
#pragma unroll
        for (int k = 0; k < NB; k++) {
            float ck = 10.0f + 20.0f * (float)k;
            float th = (ck / 180.0f) * PIF;
            float sn = sinf(th), cs = cosf(th);
            float hn = g_hog[(b * NB + k) * (OH * OW) + p] / maxn;
            float h2 = hn * hn;
            A  += (sn * sn) * h2;
            Cc += (cs * cs) * h2;
            Bs += (sn * cs) * h2;
        }
        float Bb = -Bs;
        float half = (A - Cc) * 0.5f;
        float lam = (A + Cc) * 0.5f + sqrtf(half * half + Bb * Bb);
        float la = lam - A, lc = lam - Cc;
        float n1 = Bb * Bb + la * la;
        float n2 = lc * lc + Bb * Bb;
        bool use1 = (n1 >= n2);
        float vx = use1 ? Bb : lc;
        float vy = use1 ? la : Bb;
        float nrm = sqrtf(vx * vx + vy * vy) + 1e-9f;
        qs[0][tid] = floorf((vx / nrm + 1.0f) / 2.0f * 255.0f);
        qs[1][tid] = floorf((vy / nrm + 1.0f) / 2.0f * 255.0f);
    }
    __syncthreads();

    // horizontal pass: 2 channels x 512 outputs
    for (int i = tid; i < 2 * WW; i += 256) {
        int c = i >> 9;
        int xo = i & 511;
        int st = g_ws[xo];
        float s = 0.0f;
#pragma unroll
        for (int j = 0; j < 6; j++) {
            int idx = min(max(st + j, 0), OW - 1);
            s += g_wt[xo * 6 + j] * qs[c][idx];
        }
        g_tmp[(b * 2 + c) * (OH * WW) + row * WW + xo] = s;
    }
}

// ---------------- vertical pass + epilogue: 8 rows/block, taps in registers, float2/thread ----------------
// st = g_ws[y] is constant across each aligned 8-row group, so the 6 tap rows
// (x 2 channels = 12 float2 loads) are loaded ONCE per thread and reused for 8 rows.
// 256 threads x 2 px keeps regs ~40 -> high occupancy for latency hiding.
__global__ void vpass_kernel(float* __restrict__ out) {
    int gid = blockIdx.x;              // b * 64 + group
    int b = gid >> 6;
    int grp = gid & 63;
    int y0 = grp * 8;
    int x2 = threadIdx.x * 2;          // 256 threads x 2 pixels

    int st = __ldg(&g_ws[y0]);         // identical for all 8 rows in this group
    const float* t0 = g_tmp + (b * 2 + 0) * (OH * WW);
    const float* t1 = g_tmp + (b * 2 + 1) * (OH * WW);

    float2 ta[6], tc[6];
#pragma unroll
    for (int j = 0; j < 6; j++) {
        int ro = min(max(st + j, 0), OH - 1) * WW;
        ta[j] = __ldg((const float2*)(t0 + ro + x2));
        tc[j] = __ldg((const float2*)(t1 + ro + x2));
    }

    float* base0 = out + ((size_t)(b * 2 + 0) * HH + y0) * WW + x2;
    float* base1 = out + ((size_t)(b * 2 + 1) * HH + y0) * WW + x2;

#pragma unroll
    for (int ry = 0; ry < 8; ry++) {
        int y = y0 + ry;
        float2 r0 = make_float2(0.f, 0.f);
        float2 r1 = make_float2(0.f, 0.f);
#pragma unroll
        for (int j = 0; j < 6; j++) {
            float wj = __ldg(&g_wt[y * 6 + j]);
            r0.x += wj * ta[j].x; r0.y += wj * ta[j].y;
            r1.x += wj * tc[j].x; r1.y += wj * tc[j].y;
        }

        float2 o0, o1;
        float* pr0 = &r0.x; float* pr1 = &r1.x;
        float* po0 = &o0.x; float* po1 = &o1.x;
#pragma unroll
        for (int q = 0; q < 2; q++) {
            float a = fminf(fmaxf(rintf(pr0[q]), 0.0f), 255.0f);
            float c = fminf(fmaxf(rintf(pr1[q]), 0.0f), 255.0f);
            float u = fmaf(a, 0.003921568859f, -0.5f) * 2.0f;
            float v = fmaf(c, 0.003921568859f, -0.5f) * 2.0f;
            float rn = __frsqrt_rn(fmaf(u, u, v * v));
            po0[q] = u * rn;
            po1[q] = v * rn;
        }
        *(float2*)(base0 + ry * WW) = o0;
        *(float2*)(base1 + ry * WW) = o1;
    }
}

// ---------------- launch ----------------
extern "C" void kernel_launch(void* const* d_in, const int* in_sizes, int n_in,
                              void* d_out, int out_size) {
    const float* x = (const float*)d_in[0];
    int B = in_sizes[0] / (3 * HH * WW);
    if (B > BMAX) B = BMAX;

    grad_kernel<<<dim3(WW / 32, HH / 8, B), dim3(32, 8)>>>(x);
    hog_kernel<<<dim3(OH * OW, B), 256>>>();
    domh_kernel<<<dim3(OH, B), 256>>>();
    vpass_kernel<<<B * 64, 256>>>((float*)d_out);
}

// round 14
// speedup vs baseline: 1.0390x; 1.0390x over previous
#include <cuda_runtime.h>

constexpr int HH = 512;
constexpr int WW = 512;
constexpr int NB = 9;
constexpr int OH = 32;
constexpr int OW = 32;
constexpr int BMAX = 8;

#define PIF 3.14159265358979323846f

// ---------------- scratch ----------------
// g_vab.x carries k0 in its low 3 mantissa bits (<=7 ulp perturbation of va)
__device__ float2 g_vab[BMAX * HH * WW];
__device__ float g_hog [BMAX * NB * OH * OW];
__device__ float g_maxn[BMAX];                     // atomicMax accumulator (>=0)
__device__ float g_tmp [BMAX * 2 * OH * WW];       // horizontally-resized rows
__device__ float g_wt  [WW * 6];
__device__ int   g_ws  [WW];

// ---------------- fused grayscale + gradient + bin decomposition (+ lanczos wt fold) ----------------
__global__ void grad_kernel(const float* __restrict__ x) {
    __shared__ float sg[10][34];
    int b = blockIdx.z;
    int x0 = blockIdx.x * 32, y0 = blockIdx.y * 8;
    const float* xb = x + (size_t)b * 3 * HH * WW;
    int tid = threadIdx.y * 32 + threadIdx.x;

    if (tid == 0) g_maxn[b] = 0.0f;   // reset for hog's atomicMax

    // fold: lanczos3 weight table, computed once by the first row of blocks of batch 0
    if (blockIdx.z == 0 && blockIdx.y == 0) {
        int o = blockIdx.x * 256 + tid;
        if (o < WW) {
            float sf = (o + 0.5f) * 0.0625f - 0.5f;
            int i0 = (int)floorf(sf) - 2;
            float w[6];
            float tot = 0.0f;
#pragma unroll
            for (int j = 0; j < 6; j++) {
                int ii = i0 + j;
                float val = 0.0f;
                if (ii >= 0 && ii < OW) {
                    float xx = fabsf(sf - (float)ii);
                    float px1 = PIF * xx;
                    float s1 = (xx == 0.0f) ? 1.0f : (sinf(px1) / px1);
                    float x3 = xx / 3.0f;
                    float px3 = PIF * x3;
                    float s3 = (x3 == 0.0f) ? 1.0f : (sinf(px3) / px3);
                    val = 3.0f * s1 * s3;
                }
                w[j] = val;
                tot += val;
            }
#pragma unroll
            for (int j = 0; j < 6; j++) g_wt[o * 6 + j] = w[j] / tot;
            g_ws[o] = i0;
        }
    }

    for (int i = tid; i < 10 * 34; i += 256) {
        int ly = i / 34, lx = i - ly * 34;
        int gy = y0 + ly - 1, gx = x0 + lx - 1;
        float v = 0.0f;
        if (gy >= 0 && gy < HH && gx >= 0 && gx < WW) {
            int p = gy * WW + gx;
            v = 0.299f * xb[p] + 0.587f * xb[p + HH * WW] + 0.114f * xb[p + 2 * HH * WW];
        }
        sg[ly][lx] = v;
    }
    __syncthreads();

    int lx = threadIdx.x, ly = threadIdx.y;
    float gx = sg[ly + 1][lx + 2] - sg[ly + 1][lx];
    float gy = sg[ly + 2][lx + 1] - sg[ly][lx + 1];
    float inten = sqrtf(gx * gx + gy * gy);
    float a = atan2f(gy, gx) + PIF;      // >= 0
    float r = fmodf(a, PIF);             // jnp.mod (positive arg) == fmod
    float o = r / PIF * 180.0f;          // [0,180)

    int k0 = (int)floorf((o - 10.0f) * 0.05f);   // [-1,8]
    float c0 = 10.0f + 20.0f * (float)k0;
    float wa = fminf(fmaxf(1.0f - (fabsf(o - c0) * 9.0f) / 180.0f, 0.0f), 1.0f);
    float wb = fminf(fmaxf(1.0f - (fabsf(o - (c0 + 20.0f)) * 9.0f) / 180.0f, 0.0f), 1.0f);
    float va = wa * inten, vb = wb * inten;
    if (k0 < 0)      { k0 = 0; va = vb; vb = 0.0f; }
    else if (k0 > 7) { k0 = 7; vb = va; va = 0.0f; }

    // pack k0 into low 3 mantissa bits of va (va >= 0; <=7 ulp perturbation)
    unsigned ua = (__float_as_uint(va) & 0xFFFFFFF8u) | (unsigned)k0;
    int p = b * HH * WW + (y0 + ly) * WW + (x0 + lx);
    g_vab[p] = make_float2(__uint_as_float(ua), vb);
}

__device__ __forceinline__ int refl(int m) {
    m = (m < 0) ? -m : m;
    m = (m > HH - 1) ? (2 * (HH - 1) - m) : m;
    return m;
}

// ---------------- HOG aggregation + fused per-cell norm -> atomicMax ----------------
__global__ void hog_kernel() {
    __shared__ float sacc[NB][256];     // bank(tid) independent of bin -> conflict-free
    __shared__ int srow[33], scol[33];
    __shared__ float sbin[NB];
    int b = blockIdx.y;
    int cell = blockIdx.x;
    int oy = cell >> 5, ox = cell & 31;
    int tid = threadIdx.x;

    if (tid < 33) {
        srow[tid] = refl(oy * 16 - 16 + tid) * WW;
        scol[tid] = refl(ox * 16 - 16 + tid);
    }
#pragma unroll
    for (int k = 0; k < NB; k++) sacc[k][tid] = 0.0f;
    __syncthreads();

    const float2* __restrict__ V = g_vab + b * HH * WW;

    // 1089 taps: 4 per thread + tail of 65 (ONE 8B load per tap; k0 in mantissa)
    float2 v[4]; float f[4]; int kk[4];
#pragma unroll
    for (int j = 0; j < 4; j++) {
        int t = tid + j * 256;
        int dy = t / 33;
        int dx = t - dy * 33;
        int gi = srow[dy] + scol[dx];
        v[j] = __ldg(&V[gi]);
        kk[j] = (int)(__float_as_uint(v[j].x) & 7u);
        float fy = (float)(dy - 16), fx = (float)(dx - 16);
        f[j] = 1.0f - sqrtf(fy * fy + fx * fx) / 22.627417f;
    }
#pragma unroll
    for (int j = 0; j < 4; j++) {
        sacc[kk[j]][tid]     += f[j] * v[j].x;
        sacc[kk[j] + 1][tid] += f[j] * v[j].y;
    }
    if (tid < 65) {
        int t = 1024 + tid;
        int dy = t / 33;
        int dx = t - dy * 33;
        int gi = srow[dy] + scol[dx];
        float2 vt = __ldg(&V[gi]);
        int kt = (int)(__float_as_uint(vt.x) & 7u);
        float fy = (float)(dy - 16), fx = (float)(dx - 16);
        float ft = 1.0f - sqrtf(fy * fy + fx * fx) / 22.627417f;
        sacc[kt][tid]     += ft * vt.x;
        sacc[kt + 1][tid] += ft * vt.y;
    }
    __syncthreads();

    // warp w reduces bins k = w, w+8 (strided LDS + shuffle tree)
    int w = tid >> 5, l = tid & 31;
    for (int k = w; k < NB; k += 8) {
        float s = 0.0f;
#pragma unroll
        for (int i = 0; i < 8; i++) s += sacc[k][l + 32 * i];
#pragma unroll
        for (int off = 16; off > 0; off >>= 1)
            s += __shfl_down_sync(0xffffffffu, s, off);
        if (l == 0) {
            g_hog[(b * NB + k) * (OH * OW) + cell] = s;
            sbin[k] = s;
        }
    }
    __syncthreads();

    // cell L2 norm over bins -> per-batch max (atomic on int view; all values >= 0)
    if (tid == 0) {
        float s2 = 0.0f;
#pragma unroll
        for (int k = 0; k < NB; k++) s2 += sbin[k] * sbin[k];
        atomicMax((int*)&g_maxn[b], __float_as_int(sqrtf(s2)));
    }
}

// ---------------- fused dominant-direction + quantize + horizontal lanczos pass ----------------
// block = (row, b): dom for 32 cells of this row (threads 0-31), then hpass 2ch x 512.
__global__ void domh_kernel() {
    __shared__ float qs[2][OW];
    int b = blockIdx.y;
    int row = blockIdx.x;              // 0..31
    int tid = threadIdx.x;             // 256

    if (tid < OW) {
        int p = row * OW + tid;
        float maxn = g_maxn[b];
        float A = 0.0f, Cc = 0.0f, Bs = 0.0f;
#pragma unroll
        for (int k = 0; k < NB; k++) {
            float ck = 10.0f + 20.0f * (float)k;
            float th = (ck / 180.0f) * PIF;
            float sn = sinf(th), cs = cosf(th);
            float hn = g_hog[(b * NB + k) * (OH * OW) + p] / maxn;
            float h2 = hn * hn;
            A  += (sn * sn) * h2;
            Cc += (cs * cs) * h2;
            Bs += (sn * cs) * h2;
        }
        float Bb = -Bs;
        float half = (A - Cc) * 0.5f;
        float lam = (A + Cc) * 0.5f + sqrtf(half * half + Bb * Bb);
        float la = lam - A, lc = lam - Cc;
        float n1 = Bb * Bb + la * la;
        float n2 = lc * lc + Bb * Bb;
        bool use1 = (n1 >= n2);
        float vx = use1 ? Bb : lc;
        float vy = use1 ? la : Bb;
        float nrm = sqrtf(vx * vx + vy * vy) + 1e-9f;
        qs[0][tid] = floorf((vx / nrm + 1.0f) / 2.0f * 255.0f);
        qs[1][tid] = floorf((vy / nrm + 1.0f) / 2.0f * 255.0f);
    }
    __syncthreads();

    // horizontal pass: 2 channels x 512 outputs
    for (int i = tid; i < 2 * WW; i += 256) {
        int c = i >> 9;
        int xo = i & 511;
        int st = g_ws[xo];
        float s = 0.0f;
#pragma unroll
        for (int j = 0; j < 6; j++) {
            int idx = min(max(st + j, 0), OW - 1);
            s += g_wt[xo * 6 + j] * qs[c][idx];
        }
        g_tmp[(b * 2 + c) * (OH * WW) + row * WW + xo] = s;
    }
}

// ---------------- vertical pass + epilogue: 8 rows/block, taps in registers (round-12 best) ----------------
__global__ void vpass_kernel(float* __restrict__ out) {
    int gid = blockIdx.x;              // b * 64 + group
    int b = gid >> 6;
    int grp = gid & 63;
    int y0 = grp * 8;
    int x4 = threadIdx.x * 4;          // 128 threads x 4 pixels

    int st = __ldg(&g_ws[y0]);         // identical for all 8 rows in this group
    const float* t0 = g_tmp + (b * 2 + 0) * (OH * WW);
    const float* t1 = g_tmp + (b * 2 + 1) * (OH * WW);

    float4 ta[6], tc[6];
#pragma unroll
    for (int j = 0; j < 6; j++) {
        int ro = min(max(st + j, 0), OH - 1) * WW;
        ta[j] = __ldg((const float4*)(t0 + ro + x4));
        tc[j] = __ldg((const float4*)(t1 + ro + x4));
    }

    float* base0 = out + ((size_t)(b * 2 + 0) * HH + y0) * WW + x4;
    float* base1 = out + ((size_t)(b * 2 + 1) * HH + y0) * WW + x4;

#pragma unroll
    for (int ry = 0; ry < 8; ry++) {
        int y = y0 + ry;
        float4 r0 = make_float4(0.f, 0.f, 0.f, 0.f);
        float4 r1 = make_float4(0.f, 0.f, 0.f, 0.f);
#pragma unroll
        for (int j = 0; j < 6; j++) {
            float wj = __ldg(&g_wt[y * 6 + j]);
            r0.x += wj * ta[j].x; r0.y += wj * ta[j].y; r0.z += wj * ta[j].z; r0.w += wj * ta[j].w;
            r1.x += wj * tc[j].x; r1.y += wj * tc[j].y; r1.z += wj * tc[j].z; r1.w += wj * tc[j].w;
        }

        float4 o0, o1;
        float* pr0 = &r0.x; float* pr1 = &r1.x;
        float* po0 = &o0.x; float* po1 = &o1.x;
#pragma unroll
        for (int q = 0; q < 4; q++) {
            float a = fminf(fmaxf(rintf(pr0[q]), 0.0f), 255.0f);
            float c = fminf(fmaxf(rintf(pr1[q]), 0.0f), 255.0f);
            float u = fmaf(a, 0.003921568859f, -0.5f) * 2.0f;
            float v = fmaf(c, 0.003921568859f, -0.5f) * 2.0f;
            float rn = __frsqrt_rn(fmaf(u, u, v * v));
            po0[q] = u * rn;
            po1[q] = v * rn;
        }
        *(float4*)(base0 + ry * WW) = o0;
        *(float4*)(base1 + ry * WW) = o1;
    }
}

// ---------------- launch ----------------
extern "C" void kernel_launch(void* const* d_in, const int* in_sizes, int n_in,
                              void* d_out, int out_size) {
    const float* x = (const float*)d_in[0];
    int B = in_sizes[0] / (3 * HH * WW);
    if (B > BMAX) B = BMAX;

    grad_kernel<<<dim3(WW / 32, HH / 8, B), dim3(32, 8)>>>(x);
    hog_kernel<<<dim3(OH * OW, B), 256>>>();
    domh_kernel<<<dim3(OH, B), 256>>>();
    vpass_kernel<<<B * 64, 128>>>((float*)d_out);
}

// round 15
// speedup vs baseline: 1.0934x; 1.0523x over previous
#include <cuda_runtime.h>

constexpr int HH = 512;
constexpr int WW = 512;
constexpr int NB = 9;
constexpr int OH = 32;
constexpr int OW = 32;
constexpr int BMAX = 8;

#define PIF 3.14159265358979323846f

// ---------------- scratch ----------------
// g_vab.x carries k0 in its low 3 mantissa bits (<=7 ulp perturbation of va)
__device__ float2 g_vab[BMAX * HH * WW];
__device__ float g_hog [BMAX * NB * OH * OW];
__device__ float g_maxn[BMAX];                     // atomicMax accumulator (>=0)
__device__ float g_tmp [BMAX * 2 * OH * WW];       // horizontally-resized rows
__device__ float g_wt  [WW * 6];
__device__ int   g_ws  [WW];

// ---------------- fused grayscale + gradient + bin decomposition (+ lanczos wt fold) ----------------
__global__ void grad_kernel(const float* __restrict__ x) {
    __shared__ float sg[10][34];
    int b = blockIdx.z;
    int x0 = blockIdx.x * 32, y0 = blockIdx.y * 8;
    const float* xb = x + (size_t)b * 3 * HH * WW;
    int tid = threadIdx.y * 32 + threadIdx.x;

    if (tid == 0) g_maxn[b] = 0.0f;   // reset for hog's atomicMax

    // fold: lanczos3 weight table, computed once by the first row of blocks of batch 0
    if (blockIdx.z == 0 && blockIdx.y == 0) {
        int o = blockIdx.x * 256 + tid;
        if (o < WW) {
            float sf = (o + 0.5f) * 0.0625f - 0.5f;
            int i0 = (int)floorf(sf) - 2;
            float w[6];
            float tot = 0.0f;
#pragma unroll
            for (int j = 0; j < 6; j++) {
                int ii = i0 + j;
                float val = 0.0f;
                if (ii >= 0 && ii < OW) {
                    float xx = fabsf(sf - (float)ii);
                    float px1 = PIF * xx;
                    float s1 = (xx == 0.0f) ? 1.0f : (sinf(px1) / px1);
                    float x3 = xx / 3.0f;
                    float px3 = PIF * x3;
                    float s3 = (x3 == 0.0f) ? 1.0f : (sinf(px3) / px3);
                    val = 3.0f * s1 * s3;
                }
                w[j] = val;
                tot += val;
            }
#pragma unroll
            for (int j = 0; j < 6; j++) g_wt[o * 6 + j] = w[j] / tot;
            g_ws[o] = i0;
        }
    }

    for (int i = tid; i < 10 * 34; i += 256) {
        int ly = i / 34, lx = i - ly * 34;
        int gy = y0 + ly - 1, gx = x0 + lx - 1;
        float v = 0.0f;
        if (gy >= 0 && gy < HH && gx >= 0 && gx < WW) {
            int p = gy * WW + gx;
            v = 0.299f * xb[p] + 0.587f * xb[p + HH * WW] + 0.114f * xb[p + 2 * HH * WW];
        }
        sg[ly][lx] = v;
    }
    __syncthreads();

    int lx = threadIdx.x, ly = threadIdx.y;
    float gx = sg[ly + 1][lx + 2] - sg[ly + 1][lx];
    float gy = sg[ly + 2][lx + 1] - sg[ly][lx + 1];
    float inten = sqrtf(gx * gx + gy * gy);

    // orientation in degrees [0,180) of the line through (gx,gy):
    // o = mod(atan2(gy,gx)+pi, pi)/pi*180. Equivalent: a = atan(min/max)-based
    // angle in [0,90]; same-sign quadrant -> a, opposite-sign -> 180-a.
    // Minimax atan poly (~1e-6 rad); tent weights are continuous in o, so this
    // error is invisible at the 1e-3 output tolerance.
    float ax = fabsf(gx), ay = fabsf(gy);
    float mn = fminf(ax, ay), mx = fmaxf(ax, ay);
    float t = mn / (mx + 1e-30f);
    float t2 = t * t;
    float p = t * (0.99997726f + t2 * (-0.33262347f + t2 * (0.19354346f +
              t2 * (-0.11643287f + t2 * (0.05265332f + t2 * (-0.01172120f))))));
    float arad = (ay > ax) ? (1.5707963267948966f - p) : p;   // [0, pi/2]
    float o = ((gx * gy) < 0.0f) ? (PIF - arad) : arad;
    o = o * (180.0f / PIF);

    int k0 = (int)floorf((o - 10.0f) * 0.05f);   // [-1,8]
    float c0 = 10.0f + 20.0f * (float)k0;
    float wa = fminf(fmaxf(1.0f - (fabsf(o - c0) * 9.0f) / 180.0f, 0.0f), 1.0f);
    float wb = fminf(fmaxf(1.0f - (fabsf(o - (c0 + 20.0f)) * 9.0f) / 180.0f, 0.0f), 1.0f);
    float va = wa * inten, vb = wb * inten;
    if (k0 < 0)      { k0 = 0; va = vb; vb = 0.0f; }
    else if (k0 > 7) { k0 = 7; vb = va; va = 0.0f; }

    // pack k0 into low 3 mantissa bits of va (va >= 0; <=7 ulp perturbation)
    unsigned ua = (__float_as_uint(va) & 0xFFFFFFF8u) | (unsigned)k0;
    int pp = b * HH * WW + (y0 + ly) * WW + (x0 + lx);
    g_vab[pp] = make_float2(__uint_as_float(ua), vb);
}

__device__ __forceinline__ int refl(int m) {
    m = (m < 0) ? -m : m;
    m = (m > HH - 1) ? (2 * (HH - 1) - m) : m;
    return m;
}

// ---------------- HOG aggregation + fused per-cell norm -> atomicMax ----------------
__global__ void hog_kernel() {
    __shared__ float sacc[NB][256];     // bank(tid) independent of bin -> conflict-free
    __shared__ int srow[33], scol[33];
    __shared__ float sbin[NB];
    int b = blockIdx.y;
    int cell = blockIdx.x;
    int oy = cell >> 5, ox = cell & 31;
    int tid = threadIdx.x;

    if (tid < 33) {
        srow[tid] = refl(oy * 16 - 16 + tid) * WW;
        scol[tid] = refl(ox * 16 - 16 + tid);
    }
#pragma unroll
    for (int k = 0; k < NB; k++) sacc[k][tid] = 0.0f;
    __syncthreads();

    const float2* __restrict__ V = g_vab + b * HH * WW;

    // 1089 taps: 4 per thread + tail of 65 (ONE 8B load per tap; k0 in mantissa)
    float2 v[4]; float f[4]; int kk[4];
#pragma unroll
    for (int j = 0; j < 4; j++) {
        int t = tid + j * 256;
        int dy = t / 33;
        int dx = t - dy * 33;
        int gi = srow[dy] + scol[dx];
        v[j] = __ldg(&V[gi]);
        kk[j] = (int)(__float_as_uint(v[j].x) & 7u);
        float fy = (float)(dy - 16), fx = (float)(dx - 16);
        f[j] = 1.0f - sqrtf(fy * fy + fx * fx) / 22.627417f;
    }
#pragma unroll
    for (int j = 0; j < 4; j++) {
        sacc[kk[j]][tid]     += f[j] * v[j].x;
        sacc[kk[j] + 1][tid] += f[j] * v[j].y;
    }
    if (tid < 65) {
        int t = 1024 + tid;
        int dy = t / 33;
        int dx = t - dy * 33;
        int gi = srow[dy] + scol[dx];
        float2 vt = __ldg(&V[gi]);
        int kt = (int)(__float_as_uint(vt.x) & 7u);
        float fy = (float)(dy - 16), fx = (float)(dx - 16);
        float ft = 1.0f - sqrtf(fy * fy + fx * fx) / 22.627417f;
        sacc[kt][tid]     += ft * vt.x;
        sacc[kt + 1][tid] += ft * vt.y;
    }
    __syncthreads();

    // warp w reduces bins k = w, w+8 (strided LDS + shuffle tree)
    int w = tid >> 5, l = tid & 31;
    for (int k = w; k < NB; k += 8) {
        float s = 0.0f;
#pragma unroll
        for (int i = 0; i < 8; i++) s += sacc[k][l + 32 * i];
#pragma unroll
        for (int off = 16; off > 0; off >>= 1)
            s += __shfl_down_sync(0xffffffffu, s, off);
        if (l == 0) {
            g_hog[(b * NB + k) * (OH * OW) + cell] = s;
            sbin[k] = s;
        }
    }
    __syncthreads();

    // cell L2 norm over bins -> per-batch max (atomic on int view; all values >= 0)
    if (tid == 0) {
        float s2 = 0.0f;
#pragma unroll
        for (int k = 0; k < NB; k++) s2 += sbin[k] * sbin[k];
        atomicMax((int*)&g_maxn[b], __float_as_int(sqrtf(s2)));
    }
}

// ---------------- fused dominant-direction + quantize + horizontal lanczos pass ----------------
// block = (row, b): dom for 32 cells of this row (threads 0-31), then hpass 2ch x 512.
__global__ void domh_kernel() {
    __shared__ float qs[2][OW];
    int b = blockIdx.y;
    int row = blockIdx.x;              // 0..31
    int tid = threadIdx.x;             // 256

    if (tid < OW) {
        int p = row * OW + tid;
        float maxn = g_maxn[b];
        float A = 0.0f, Cc = 0.0f, Bs = 0.0f;
#pragma unroll
        for (int k = 0; k < NB; k++) {
            float ck = 10.0f + 20.0f * (float)k;
            float th = (ck / 180.0f) * PIF;
            float sn = sinf(th), cs = cosf(th);
            float hn = g_hog[(b * NB + k) * (OH * OW) + p] / maxn;
            float h2 = hn * hn;
            A  += (sn * sn) * h2;
            Cc += (cs * cs) * h2;
            Bs += (sn * cs) * h2;
        }
        float Bb = -Bs;
        float half = (A - Cc) * 0.5f;
        float lam = (A + Cc) * 0.5f + sqrtf(half * half + Bb * Bb);
        float la = lam - A, lc = lam - Cc;
        float n1 = Bb * Bb + la * la;
        float n2 = lc * lc + Bb * Bb;
        bool use1 = (n1 >= n2);
        float vx = use1 ? Bb : lc;
        float vy = use1 ? la : Bb;
        float nrm = sqrtf(vx * vx + vy * vy) + 1e-9f;
        qs[0][tid] = floorf((vx / nrm + 1.0f) / 2.0f * 255.0f);
        qs[1][tid] = floorf((vy / nrm + 1.0f) / 2.0f * 255.0f);
    }
    __syncthreads();

    // horizontal pass: 2 channels x 512 outputs
    for (int i = tid; i < 2 * WW; i += 256) {
        int c = i >> 9;
        int xo = i & 511;
        int st = g_ws[xo];
        float s = 0.0f;
#pragma unroll
        for (int j = 0; j < 6; j++) {
            int idx = min(max(st + j, 0), OW - 1);
            s += g_wt[xo * 6 + j] * qs[c][idx];
        }
        g_tmp[(b * 2 + c) * (OH * WW) + row * WW + xo] = s;
    }
}

// ---------------- vertical pass + epilogue: 8 rows/block, taps in registers ----------------
__global__ void vpass_kernel(float* __restrict__ out) {
    int gid = blockIdx.x;              // b * 64 + group
    int b = gid >> 6;
    int grp = gid & 63;
    int y0 = grp * 8;
    int x4 = threadIdx.x * 4;          // 128 threads x 4 pixels

    int st = __ldg(&g_ws[y0]);         // identical for all 8 rows in this group
    const float* t0 = g_tmp + (b * 2 + 0) * (OH * WW);
    const float* t1 = g_tmp + (b * 2 + 1) * (OH * WW);

    float4 ta[6], tc[6];
#pragma unroll
    for (int j = 0; j < 6; j++) {
        int ro = min(max(st + j, 0), OH - 1) * WW;
        ta[j] = __ldg((const float4*)(t0 + ro + x4));
        tc[j] = __ldg((const float4*)(t1 + ro + x4));
    }

    float* base0 = out + ((size_t)(b * 2 + 0) * HH + y0) * WW + x4;
    float* base1 = out + ((size_t)(b * 2 + 1) * HH + y0) * WW + x4;

#pragma unroll
    for (int ry = 0; ry < 8; ry++) {
        int y = y0 + ry;
        float4 r0 = make_float4(0.f, 0.f, 0.f, 0.f);
        float4 r1 = make_float4(0.f, 0.f, 0.f, 0.f);
#pragma unroll
        for (int j = 0; j < 6; j++) {
            float wj = __ldg(&g_wt[y * 6 + j]);
            r0.x += wj * ta[j].x; r0.y += wj * ta[j].y; r0.z += wj * ta[j].z; r0.w += wj * ta[j].w;
            r1.x += wj * tc[j].x; r1.y += wj * tc[j].y; r1.z += wj * tc[j].z; r1.w += wj * tc[j].w;
        }

        float4 o0, o1;
        float* pr0 = &r0.x; float* pr1 = &r1.x;
        float* po0 = &o0.x; float* po1 = &o1.x;
#pragma unroll
        for (int q = 0; q < 4; q++) {
            float a = fminf(fmaxf(rintf(pr0[q]), 0.0f), 255.0f);
            float c = fminf(fmaxf(rintf(pr1[q]), 0.0f), 255.0f);
            float u = fmaf(a, 0.003921568859f, -0.5f) * 2.0f;
            float v = fmaf(c, 0.003921568859f, -0.5f) * 2.0f;
            float rn = __frsqrt_rn(fmaf(u, u, v * v));
            po0[q] = u * rn;
            po1[q] = v * rn;
        }
        *(float4*)(base0 + ry * WW) = o0;
        *(float4*)(base1 + ry * WW) = o1;
    }
}

// ---------------- launch ----------------
extern "C" void kernel_launch(void* const* d_in, const int* in_sizes, int n_in,
                              void* d_out, int out_size) {
    const float* x = (const float*)d_in[0];
    int B = in_sizes[0] / (3 * HH * WW);
    if (B > BMAX) B = BMAX;

    grad_kernel<<<dim3(WW / 32, HH / 8, B), dim3(32, 8)>>>(x);
    hog_kernel<<<dim3(OH * OW, B), 256>>>();
    domh_kernel<<<dim3(OH, B), 256>>>();
    vpass_kernel<<<B * 64, 128>>>((float*)d_out);
}

// round 16
// speedup vs baseline: 1.1147x; 1.0195x over previous
#include <cuda_runtime.h>

constexpr int HH = 512;
constexpr int WW = 512;
constexpr int NB = 9;
constexpr int OH = 32;
constexpr int OW = 32;
constexpr int BMAX = 8;

#define PIF 3.14159265358979323846f

// ---------------- scratch ----------------
// g_vab.x carries k0 in its low 3 mantissa bits (<=7 ulp perturbation of va)
__device__ float2 g_vab[BMAX * HH * WW];
__device__ float g_hog [BMAX * NB * OH * OW];
__device__ float g_maxn[BMAX];                     // atomicMax accumulator (>=0)
__device__ float g_tmp [BMAX * 2 * OH * WW];       // horizontally-resized rows
__device__ float g_wt  [WW * 6];
__device__ int   g_ws  [WW];

// ---------------- fused grayscale + gradient + bin decomposition (+ lanczos wt fold) ----------------
__global__ void grad_kernel(const float* __restrict__ x) {
    __shared__ float sg[10][34];
    int b = blockIdx.z;
    int x0 = blockIdx.x * 32, y0 = blockIdx.y * 8;
    const float* xb = x + (size_t)b * 3 * HH * WW;
    int tid = threadIdx.y * 32 + threadIdx.x;

    if (tid == 0) g_maxn[b] = 0.0f;   // reset for hog's atomicMax

    // fold: lanczos3 weight table, computed once by the first row of blocks of batch 0
    if (blockIdx.z == 0 && blockIdx.y == 0) {
        int o = blockIdx.x * 256 + tid;
        if (o < WW) {
            float sf = (o + 0.5f) * 0.0625f - 0.5f;
            int i0 = (int)floorf(sf) - 2;
            float w[6];
            float tot = 0.0f;
#pragma unroll
            for (int j = 0; j < 6; j++) {
                int ii = i0 + j;
                float val = 0.0f;
                if (ii >= 0 && ii < OW) {
                    float xx = fabsf(sf - (float)ii);
                    float px1 = PIF * xx;
                    float s1 = (xx == 0.0f) ? 1.0f : (sinf(px1) / px1);
                    float x3 = xx / 3.0f;
                    float px3 = PIF * x3;
                    float s3 = (x3 == 0.0f) ? 1.0f : (sinf(px3) / px3);
                    val = 3.0f * s1 * s3;
                }
                w[j] = val;
                tot += val;
            }
#pragma unroll
            for (int j = 0; j < 6; j++) g_wt[o * 6 + j] = w[j] / tot;
            g_ws[o] = i0;
        }
    }

    for (int i = tid; i < 10 * 34; i += 256) {
        int ly = i / 34, lx = i - ly * 34;
        int gy = y0 + ly - 1, gx = x0 + lx - 1;
        float v = 0.0f;
        if (gy >= 0 && gy < HH && gx >= 0 && gx < WW) {
            int p = gy * WW + gx;
            v = 0.299f * xb[p] + 0.587f * xb[p + HH * WW] + 0.114f * xb[p + 2 * HH * WW];
        }
        sg[ly][lx] = v;
    }
    __syncthreads();

    int lx = threadIdx.x, ly = threadIdx.y;
    float gx = sg[ly + 1][lx + 2] - sg[ly + 1][lx];
    float gy = sg[ly + 2][lx + 1] - sg[ly][lx + 1];
    float inten = sqrtf(gx * gx + gy * gy);

    // orientation in degrees [0,180) via octant-reduced minimax atan (~1e-6 rad)
    float ax = fabsf(gx), ay = fabsf(gy);
    float mn = fminf(ax, ay), mx = fmaxf(ax, ay);
    float t = mn / (mx + 1e-30f);
    float t2 = t * t;
    float p = t * (0.99997726f + t2 * (-0.33262347f + t2 * (0.19354346f +
              t2 * (-0.11643287f + t2 * (0.05265332f + t2 * (-0.01172120f))))));
    float arad = (ay > ax) ? (1.5707963267948966f - p) : p;   // [0, pi/2]
    float o = ((gx * gy) < 0.0f) ? (PIF - arad) : arad;
    o = o * (180.0f / PIF);

    int k0 = (int)floorf((o - 10.0f) * 0.05f);   // [-1,8]
    float c0 = 10.0f + 20.0f * (float)k0;
    float wa = fminf(fmaxf(1.0f - (fabsf(o - c0) * 9.0f) / 180.0f, 0.0f), 1.0f);
    float wb = fminf(fmaxf(1.0f - (fabsf(o - (c0 + 20.0f)) * 9.0f) / 180.0f, 0.0f), 1.0f);
    float va = wa * inten, vb = wb * inten;
    if (k0 < 0)      { k0 = 0; va = vb; vb = 0.0f; }
    else if (k0 > 7) { k0 = 7; vb = va; va = 0.0f; }

    // pack k0 into low 3 mantissa bits of va (va >= 0; <=7 ulp perturbation)
    unsigned ua = (__float_as_uint(va) & 0xFFFFFFF8u) | (unsigned)k0;
    int pp = b * HH * WW + (y0 + ly) * WW + (x0 + lx);
    g_vab[pp] = make_float2(__uint_as_float(ua), vb);
}

__device__ __forceinline__ int refl(int m) {
    m = (m < 0) ? -m : m;
    m = (m > HH - 1) ? (2 * (HH - 1) - m) : m;
    return m;
}

// ---------------- HOG aggregation + fused per-cell norm -> atomicMax ----------------
// 128 threads, 8 batched taps/thread (MLP 8) + tail of 65.
__global__ void hog_kernel() {
    __shared__ float sacc[NB][128];     // bank(tid) independent of bin -> conflict-free
    __shared__ int srow[33], scol[33];
    __shared__ float sbin[NB];
    int b = blockIdx.y;
    int cell = blockIdx.x;
    int oy = cell >> 5, ox = cell & 31;
    int tid = threadIdx.x;              // 128

    if (tid < 33) {
        srow[tid] = refl(oy * 16 - 16 + tid) * WW;
        scol[tid] = refl(ox * 16 - 16 + tid);
    }
#pragma unroll
    for (int k = 0; k < NB; k++) sacc[k][tid] = 0.0f;
    __syncthreads();

    const float2* __restrict__ V = g_vab + b * HH * WW;

    // 1089 taps: 8 per thread (8*128=1024) + tail of 65
    float2 v[8]; float f[8]; int kk[8];
#pragma unroll
    for (int j = 0; j < 8; j++) {
        int t = tid + j * 128;
        int dy = t / 33;
        int dx = t - dy * 33;
        int gi = srow[dy] + scol[dx];
        v[j] = __ldg(&V[gi]);
        kk[j] = (int)(__float_as_uint(v[j].x) & 7u);
        float fy = (float)(dy - 16), fx = (float)(dx - 16);
        f[j] = 1.0f - sqrtf(fy * fy + fx * fx) / 22.627417f;
    }
#pragma unroll
    for (int j = 0; j < 8; j++) {
        sacc[kk[j]][tid]     += f[j] * v[j].x;
        sacc[kk[j] + 1][tid] += f[j] * v[j].y;
    }
    if (tid < 65) {
        int t = 1024 + tid;
        int dy = t / 33;
        int dx = t - dy * 33;
        int gi = srow[dy] + scol[dx];
        float2 vt = __ldg(&V[gi]);
        int kt = (int)(__float_as_uint(vt.x) & 7u);
        float fy = (float)(dy - 16), fx = (float)(dx - 16);
        float ft = 1.0f - sqrtf(fy * fy + fx * fx) / 22.627417f;
        sacc[kt][tid]     += ft * vt.x;
        sacc[kt + 1][tid] += ft * vt.y;
    }
    __syncthreads();

    // warp w (of 4) reduces bins k = w, w+4, w+8 (strided LDS + shuffle tree)
    int w = tid >> 5, l = tid & 31;
    for (int k = w; k < NB; k += 4) {
        float s = 0.0f;
#pragma unroll
        for (int i = 0; i < 4; i++) s += sacc[k][l + 32 * i];
#pragma unroll
        for (int off = 16; off > 0; off >>= 1)
            s += __shfl_down_sync(0xffffffffu, s, off);
        if (l == 0) {
            g_hog[(b * NB + k) * (OH * OW) + cell] = s;
            sbin[k] = s;
        }
    }
    __syncthreads();

    // cell L2 norm over bins -> per-batch max (atomic on int view; all values >= 0)
    if (tid == 0) {
        float s2 = 0.0f;
#pragma unroll
        for (int k = 0; k < NB; k++) s2 += sbin[k] * sbin[k];
        atomicMax((int*)&g_maxn[b], __float_as_int(sqrtf(s2)));
    }
}

// ---------------- fused dominant-direction + quantize + horizontal lanczos pass ----------------
// block = (row, b): dom for 32 cells of this row (threads 0-31), then hpass 2ch x 512.
__global__ void domh_kernel() {
    __shared__ float qs[2][OW];
    int b = blockIdx.y;
    int row = blockIdx.x;              // 0..31
    int tid = threadIdx.x;             // 256

    if (tid < OW) {
        int p = row * OW + tid;
        float maxn = g_maxn[b];
        float A = 0.0f, Cc = 0.0f, Bs = 0.0f;
#pragma unroll
        for (int k = 0; k < NB; k++) {
            float ck = 10.0f + 20.0f * (float)k;
            float th = (ck / 180.0f) * PIF;
            float sn = sinf(th), cs = cosf(th);
            float hn = g_hog[(b * NB + k) * (OH * OW) + p] / maxn;
            float h2 = hn * hn;
            A  += (sn * sn) * h2;
            Cc += (cs * cs) * h2;
            Bs += (sn * cs) * h2;
        }
        float Bb = -Bs;
        float half = (A - Cc) * 0.5f;
        float lam = (A + Cc) * 0.5f + sqrtf(half * half + Bb * Bb);
        float la = lam - A, lc = lam - Cc;
        float n1 = Bb * Bb + la * la;
        float n2 = lc * lc + Bb * Bb;
        bool use1 = (n1 >= n2);
        float vx = use1 ? Bb : lc;
        float vy = use1 ? la : Bb;
        float nrm = sqrtf(vx * vx + vy * vy) + 1e-9f;
        qs[0][tid] = floorf((vx / nrm + 1.0f) / 2.0f * 255.0f);
        qs[1][tid] = floorf((vy / nrm + 1.0f) / 2.0f * 255.0f);
    }
    __syncthreads();

    // horizontal pass: 2 channels x 512 outputs
    for (int i = tid; i < 2 * WW; i += 256) {
        int c = i >> 9;
        int xo = i & 511;
        int st = g_ws[xo];
        float s = 0.0f;
#pragma unroll
        for (int j = 0; j < 6; j++) {
            int idx = min(max(st + j, 0), OW - 1);
            s += g_wt[xo * 6 + j] * qs[c][idx];
        }
        g_tmp[(b * 2 + c) * (OH * WW) + row * WW + xo] = s;
    }
}

// ---------------- vertical pass + epilogue: 4 rows/block, taps in registers ----------------
// st = g_ws[y] is constant across aligned 8-row groups (a fortiori 4-row groups),
// so the 6 tap rows (x 2 channels = 12 float4 loads) are loaded ONCE and reused.
// grid = B*128 -> ~7 blocks/SM, fixes the occ=20% grid starvation of the 8-row form.
__global__ void vpass_kernel(float* __restrict__ out) {
    int gid = blockIdx.x;              // b * 128 + group
    int b = gid >> 7;
    int grp = gid & 127;
    int y0 = grp * 4;
    int x4 = threadIdx.x * 4;          // 128 threads x 4 pixels

    int st = __ldg(&g_ws[y0]);         // identical for all 4 rows in this group
    const float* t0 = g_tmp + (b * 2 + 0) * (OH * WW);
    const float* t1 = g_tmp + (b * 2 + 1) * (OH * WW);

    float4 ta[6], tc[6];
#pragma unroll
    for (int j = 0; j < 6; j++) {
        int ro = min(max(st + j, 0), OH - 1) * WW;
        ta[j] = __ldg((const float4*)(t0 + ro + x4));
        tc[j] = __ldg((const float4*)(t1 + ro + x4));
    }

    float* base0 = out + ((size_t)(b * 2 + 0) * HH + y0) * WW + x4;
    float* base1 = out + ((size_t)(b * 2 + 1) * HH + y0) * WW + x4;

#pragma unroll
    for (int ry = 0; ry < 4; ry++) {
        int y = y0 + ry;
        float4 r0 = make_float4(0.f, 0.f, 0.f, 0.f);
        float4 r1 = make_float4(0.f, 0.f, 0.f, 0.f);
#pragma unroll
        for (int j = 0; j < 6; j++) {
            float wj = __ldg(&g_wt[y * 6 + j]);
            r0.x += wj * ta[j].x; r0.y += wj * ta[j].y; r0.z += wj * ta[j].z; r0.w += wj * ta[j].w;
            r1.x += wj * tc[j].x; r1.y += wj * tc[j].y; r1.z += wj * tc[j].z; r1.w += wj * tc[j].w;
        }

        float4 o0, o1;
        float* pr0 = &r0.x; float* pr1 = &r1.x;
        float* po0 = &o0.x; float* po1 = &o1.x;
#pragma unroll
        for (int q = 0; q < 4; q++) {
            float a = fminf(fmaxf(rintf(pr0[q]), 0.0f), 255.0f);
            float c = fminf(fmaxf(rintf(pr1[q]), 0.0f), 255.0f);
            float u = fmaf(a, 0.003921568859f, -0.5f) * 2.0f;
            float v = fmaf(c, 0.003921568859f, -0.5f) * 2.0f;
            float rn = __frsqrt_rn(fmaf(u, u, v * v));
            po0[q] = u * rn;
            po1[q] = v * rn;
        }
        *(float4*)(base0 + ry * WW) = o0;
        *(float4*)(base1 + ry * WW) = o1;
    }
}

// ---------------- launch ----------------
extern "C" void kernel_launch(void* const* d_in, const int* in_sizes, int n_in,
                              void* d_out, int out_size) {
    const float* x = (const float*)d_in[0];
    int B = in_sizes[0] / (3 * HH * WW);
    if (B > BMAX) B = BMAX;

    grad_kernel<<<dim3(WW / 32, HH / 8, B), dim3(32, 8)>>>(x);
    hog_kernel<<<dim3(OH * OW, B), 128>>>();
    domh_kernel<<<dim3(OH, B), 256>>>();
    vpass_kernel<<<B * 128, 128>>>((float*)d_out);
}

// round 17
// speedup vs baseline: 1.3005x; 1.1667x over previous
#include <cuda_runtime.h>

constexpr int HH = 512;
constexpr int WW = 512;
constexpr int NB = 9;
constexpr int OH = 32;
constexpr int OW = 32;
constexpr int BMAX = 8;

#define PIF 3.14159265358979323846f

// ---------------- scratch ----------------
// g_vab.x carries k0 in its low 3 mantissa bits (<=7 ulp perturbation of va)
__device__ float2 g_vab[BMAX * HH * WW];
__device__ float g_hog [BMAX * NB * OH * OW];
__device__ float g_maxn[BMAX];                     // atomicMax accumulator (>=0)
__device__ float g_tmp [BMAX * 2 * OH * WW];       // horizontally-resized rows
__device__ float g_wt  [WW * 6];
__device__ int   g_ws  [WW];

// ---------------- fused grayscale + gradient + bin decomposition (+ lanczos wt fold) ----------------
// 32x32 tile per block (256 threads, 4 rows/thread); 34x34 halo (13% overhead vs 33%).
__global__ void grad_kernel(const float* __restrict__ x) {
    __shared__ float sg[34][35];
    int b = blockIdx.z;
    int x0 = blockIdx.x * 32, y0 = blockIdx.y * 32;
    const float* xb = x + (size_t)b * 3 * HH * WW;
    int tid = threadIdx.y * 32 + threadIdx.x;

    if (tid == 0 && blockIdx.x == 0 && blockIdx.y == 0) g_maxn[b] = 0.0f;

    // fold: lanczos3 weight table (blocks (0..1, 0, 0) cover o = 0..511)
    if (blockIdx.z == 0 && blockIdx.y == 0 && blockIdx.x < 2) {
        int o = blockIdx.x * 256 + tid;
        if (o < WW) {
            float sf = (o + 0.5f) * 0.0625f - 0.5f;
            int i0 = (int)floorf(sf) - 2;
            float w[6];
            float tot = 0.0f;
#pragma unroll
            for (int j = 0; j < 6; j++) {
                int ii = i0 + j;
                float val = 0.0f;
                if (ii >= 0 && ii < OW) {
                    float xx = fabsf(sf - (float)ii);
                    float px1 = PIF * xx;
                    float s1 = (xx == 0.0f) ? 1.0f : (sinf(px1) / px1);
                    float x3 = xx / 3.0f;
                    float px3 = PIF * x3;
                    float s3 = (x3 == 0.0f) ? 1.0f : (sinf(px3) / px3);
                    val = 3.0f * s1 * s3;
                }
                w[j] = val;
                tot += val;
            }
#pragma unroll
            for (int j = 0; j < 6; j++) g_wt[o * 6 + j] = w[j] / tot;
            g_ws[o] = i0;
        }
    }

    // halo load: 34x34 gray values, zero outside image
    for (int i = tid; i < 34 * 34; i += 256) {
        int ly = i / 34, lx = i - ly * 34;
        int gy = y0 + ly - 1, gx = x0 + lx - 1;
        float v = 0.0f;
        if (gy >= 0 && gy < HH && gx >= 0 && gx < WW) {
            int p = gy * WW + gx;
            v = 0.299f * __ldg(&xb[p]) + 0.587f * __ldg(&xb[p + HH * WW])
              + 0.114f * __ldg(&xb[p + 2 * HH * WW]);
        }
        sg[ly][lx] = v;
    }
    __syncthreads();

    int lx = threadIdx.x;
#pragma unroll
    for (int r = 0; r < 4; r++) {
        int ly = threadIdx.y + r * 8;
        float gx = sg[ly + 1][lx + 2] - sg[ly + 1][lx];
        float gy = sg[ly + 2][lx + 1] - sg[ly][lx + 1];
        float inten = sqrtf(gx * gx + gy * gy);

        // orientation in degrees [0,180) via octant-reduced minimax atan (~1e-6 rad)
        float ax = fabsf(gx), ay = fabsf(gy);
        float mn = fminf(ax, ay), mx = fmaxf(ax, ay);
        float t = mn / (mx + 1e-30f);
        float t2 = t * t;
        float p = t * (0.99997726f + t2 * (-0.33262347f + t2 * (0.19354346f +
                  t2 * (-0.11643287f + t2 * (0.05265332f + t2 * (-0.01172120f))))));
        float arad = (ay > ax) ? (1.5707963267948966f - p) : p;   // [0, pi/2]
        float o = ((gx * gy) < 0.0f) ? (PIF - arad) : arad;
        o = o * (180.0f / PIF);

        int k0 = (int)floorf((o - 10.0f) * 0.05f);   // [-1,8]
        float c0 = 10.0f + 20.0f * (float)k0;
        float wa = fminf(fmaxf(1.0f - (fabsf(o - c0) * 9.0f) / 180.0f, 0.0f), 1.0f);
        float wb = fminf(fmaxf(1.0f - (fabsf(o - (c0 + 20.0f)) * 9.0f) / 180.0f, 0.0f), 1.0f);
        float va = wa * inten, vb = wb * inten;
        if (k0 < 0)      { k0 = 0; va = vb; vb = 0.0f; }
        else if (k0 > 7) { k0 = 7; vb = va; va = 0.0f; }

        unsigned ua = (__float_as_uint(va) & 0xFFFFFFF8u) | (unsigned)k0;
        int pp = b * HH * WW + (y0 + ly) * WW + (x0 + lx);
        g_vab[pp] = make_float2(__uint_as_float(ua), vb);
    }
}

__device__ __forceinline__ int refl(int m) {
    m = (m < 0) ? -m : m;
    m = (m > HH - 1) ? (2 * (HH - 1) - m) : m;
    return m;
}

// ---------------- HOG aggregation + fused per-cell norm -> atomicMax ----------------
// 128 threads, 8 batched taps/thread (MLP 8) + tail of 65.
__global__ void hog_kernel() {
    __shared__ float sacc[NB][128];     // bank(tid) independent of bin -> conflict-free
    __shared__ int srow[33], scol[33];
    __shared__ float sbin[NB];
    int b = blockIdx.y;
    int cell = blockIdx.x;
    int oy = cell >> 5, ox = cell & 31;
    int tid = threadIdx.x;              // 128

    if (tid < 33) {
        srow[tid] = refl(oy * 16 - 16 + tid) * WW;
        scol[tid] = refl(ox * 16 - 16 + tid);
    }
#pragma unroll
    for (int k = 0; k < NB; k++) sacc[k][tid] = 0.0f;
    __syncthreads();

    const float2* __restrict__ V = g_vab + b * HH * WW;

    // 1089 taps: 8 per thread (8*128=1024) + tail of 65
    float2 v[8]; float f[8]; int kk[8];
#pragma unroll
    for (int j = 0; j < 8; j++) {
        int t = tid + j * 128;
        int dy = t / 33;
        int dx = t - dy * 33;
        int gi = srow[dy] + scol[dx];
        v[j] = __ldg(&V[gi]);
        kk[j] = (int)(__float_as_uint(v[j].x) & 7u);
        float fy = (float)(dy - 16), fx = (float)(dx - 16);
        f[j] = 1.0f - sqrtf(fy * fy + fx * fx) / 22.627417f;
    }
#pragma unroll
    for (int j = 0; j < 8; j++) {
        sacc[kk[j]][tid]     += f[j] * v[j].x;
        sacc[kk[j] + 1][tid] += f[j] * v[j].y;
    }
    if (tid < 65) {
        int t = 1024 + tid;
        int dy = t / 33;
        int dx = t - dy * 33;
        int gi = srow[dy] + scol[dx];
        float2 vt = __ldg(&V[gi]);
        int kt = (int)(__float_as_uint(vt.x) & 7u);
        float fy = (float)(dy - 16), fx = (float)(dx - 16);
        float ft = 1.0f - sqrtf(fy * fy + fx * fx) / 22.627417f;
        sacc[kt][tid]     += ft * vt.x;
        sacc[kt + 1][tid] += ft * vt.y;
    }
    __syncthreads();

    // warp w (of 4) reduces bins k = w, w+4, w+8 (strided LDS + shuffle tree)
    int w = tid >> 5, l = tid & 31;
    for (int k = w; k < NB; k += 4) {
        float s = 0.0f;
#pragma unroll
        for (int i = 0; i < 4; i++) s += sacc[k][l + 32 * i];
#pragma unroll
        for (int off = 16; off > 0; off >>= 1)
            s += __shfl_down_sync(0xffffffffu, s, off);
        if (l == 0) {
            g_hog[(b * NB + k) * (OH * OW) + cell] = s;
            sbin[k] = s;
        }
    }
    __syncthreads();

    // cell L2 norm over bins -> per-batch max (atomic on int view; all values >= 0)
    if (tid == 0) {
        float s2 = 0.0f;
#pragma unroll
        for (int k = 0; k < NB; k++) s2 += sbin[k] * sbin[k];
        atomicMax((int*)&g_maxn[b], __float_as_int(sqrtf(s2)));
    }
}

// ---------------- fused dominant-direction + quantize + horizontal lanczos pass ----------------
// block = (row, b): dom for 32 cells of this row (threads 0-31), then hpass 2ch x 512.
__global__ void domh_kernel() {
    __shared__ float qs[2][OW];
    int b = blockIdx.y;
    int row = blockIdx.x;              // 0..31
    int tid = threadIdx.x;             // 256

    if (tid < OW) {
        int p = row * OW + tid;
        float maxn = g_maxn[b];
        float A = 0.0f, Cc = 0.0f, Bs = 0.0f;
#pragma unroll
        for (int k = 0; k < NB; k++) {
            float ck = 10.0f + 20.0f * (float)k;
            float th = (ck / 180.0f) * PIF;
            float sn = sinf(th), cs = cosf(th);
            float hn = g_hog[(b * NB + k) * (OH * OW) + p] / maxn;
            float h2 = hn * hn;
            A  += (sn * sn) * h2;
            Cc += (cs * cs) * h2;
            Bs += (sn * cs) * h2;
        }
        float Bb = -Bs;
        float half = (A - Cc) * 0.5f;
        float lam = (A + Cc) * 0.5f + sqrtf(half * half + Bb * Bb);
        float la = lam - A, lc = lam - Cc;
        float n1 = Bb * Bb + la * la;
        float n2 = lc * lc + Bb * Bb;
        bool use1 = (n1 >= n2);
        float vx = use1 ? Bb : lc;
        float vy = use1 ? la : Bb;
        float nrm = sqrtf(vx * vx + vy * vy) + 1e-9f;
        qs[0][tid] = floorf((vx / nrm + 1.0f) / 2.0f * 255.0f);
        qs[1][tid] = floorf((vy / nrm + 1.0f) / 2.0f * 255.0f);
    }
    __syncthreads();

    // horizontal pass: 2 channels x 512 outputs
    for (int i = tid; i < 2 * WW; i += 256) {
        int c = i >> 9;
        int xo = i & 511;
        int st = g_ws[xo];
        float s = 0.0f;
#pragma unroll
        for (int j = 0; j < 6; j++) {
            int idx = min(max(st + j, 0), OW - 1);
            s += g_wt[xo * 6 + j] * qs[c][idx];
        }
        g_tmp[(b * 2 + c) * (OH * WW) + row * WW + xo] = s;
    }
}

// ---------------- vertical pass + epilogue: 2 rows/block, taps in registers ----------------
// st = g_ws[y] is constant across aligned 8-row groups (a fortiori 2-row groups).
// grid = B*256 -> ~14 blocks/SM for maximum latency hiding.
__global__ void vpass_kernel(float* __restrict__ out) {
    int gid = blockIdx.x;              // b * 256 + group
    int b = gid >> 8;
    int grp = gid & 255;
    int y0 = grp * 2;
    int x4 = threadIdx.x * 4;          // 128 threads x 4 pixels

    int st = __ldg(&g_ws[y0]);         // identical for both rows in this group
    const float* t0 = g_tmp + (b * 2 + 0) * (OH * WW);
    const float* t1 = g_tmp + (b * 2 + 1) * (OH * WW);

    float4 ta[6], tc[6];
#pragma unroll
    for (int j = 0; j < 6; j++) {
        int ro = min(max(st + j, 0), OH - 1) * WW;
        ta[j] = __ldg((const float4*)(t0 + ro + x4));
        tc[j] = __ldg((const float4*)(t1 + ro + x4));
    }

    float* base0 = out + ((size_t)(b * 2 + 0) * HH + y0) * WW + x4;
    float* base1 = out + ((size_t)(b * 2 + 1) * HH + y0) * WW + x4;

#pragma unroll
    for (int ry = 0; ry < 2; ry++) {
        int y = y0 + ry;
        float4 r0 = make_float4(0.f, 0.f, 0.f, 0.f);
        float4 r1 = make_float4(0.f, 0.f, 0.f, 0.f);
#pragma unroll
        for (int j = 0; j < 6; j++) {
            float wj = __ldg(&g_wt[y * 6 + j]);
            r0.x += wj * ta[j].x; r0.y += wj * ta[j].y; r0.z += wj * ta[j].z; r0.w += wj * ta[j].w;
            r1.x += wj * tc[j].x; r1.y += wj * tc[j].y; r1.z += wj * tc[j].z; r1.w += wj * tc[j].w;
        }

        float4 o0, o1;
        float* pr0 = &r0.x; float* pr1 = &r1.x;
        float* po0 = &o0.x; float* po1 = &o1.x;
#pragma unroll
        for (int q = 0; q < 4; q++) {
            float a = fminf(fmaxf(rintf(pr0[q]), 0.0f), 255.0f);
            float c = fminf(fmaxf(rintf(pr1[q]), 0.0f), 255.0f);
            float u = fmaf(a, 0.003921568859f, -0.5f) * 2.0f;
            float v = fmaf(c, 0.003921568859f, -0.5f) * 2.0f;
            float rn = __frsqrt_rn(fmaf(u, u, v * v));
            po0[q] = u * rn;
            po1[q] = v * rn;
        }
        *(float4*)(base0 + ry * WW) = o0;
        *(float4*)(base1 + ry * WW) = o1;
    }
}

// ---------------- launch ----------------
extern "C" void kernel_launch(void* const* d_in, const int* in_sizes, int n_in,
                              void* d_out, int out_size) {
    const float* x = (const float*)d_in[0];
    int B = in_sizes[0] / (3 * HH * WW);
    if (B > BMAX) B = BMAX;

    grad_kernel<<<dim3(WW / 32, HH / 32, B), dim3(32, 8)>>>(x);
    hog_kernel<<<dim3(OH * OW, B), 128>>>();
    domh_kernel<<<dim3(OH, B), 256>>>();
    vpass_kernel<<<B * 256, 128>>>((float*)d_out);
}